// round 5
// baseline (speedup 1.0000x reference)
#include <cuda_runtime.h>
#include <stdint.h>

#define Bn 4096
#define Dn 16
#define Mn 4
#define Rn 2048
#define Cn 10
#define BT 32
#define WARPS 16
#define THREADS 512
#define HALF_R 1024
#define RPW 64          // rules per warp (HALF_R / WARPS)
#define CHUNK 16
#define EPSV 1e-9f

// scratch (module-load allocation, allowed)
__device__ uint4 g_offp[Rn];          // packed table byte-offsets
__device__ float g_cs[Rn * 12];       // folded consequents (+1.0, 0.0 pad)
__device__ float g_psum[2 * Bn];      // per-half rule-sum partials
__device__ float g_pacc[2 * Bn * Cn]; // per-half out partials
__device__ float g_sx[Bn];            // row sums of x_ext

__device__ __forceinline__ void ffma2(unsigned long long& acc,
                                      unsigned long long a,
                                      unsigned long long b) {
    asm("fma.rn.f32x2 %0, %1, %2, %0;" : "+l"(acc) : "l"(a), "l"(b));
}
__device__ __forceinline__ unsigned long long bcast2(float f) {
    unsigned long long r;
    asm("mov.b64 %0, {%1, %1};" : "=l"(r) : "f"(f));
    return r;
}

// ---------------------------------------------------------------------------
// prep: fold consequents (coalesced) + pack rule offsets. 8 rules / 256-thr CTA
// ---------------------------------------------------------------------------
__global__ void anfis_prep(const float* __restrict__ cons,
                           const int*   __restrict__ rules) {
    __shared__ float s[8 * 170];
    const int r0 = blockIdx.x * 8;
    const float* base = cons + (size_t)r0 * 170;
    for (int i = threadIdx.x; i < 8 * 170; i += 256) s[i] = base[i];
    __syncthreads();
    const int t = threadIdx.x;
    if (t < 80) {
        int rr = t / 10, c = t % 10;
        float a = 0.f;
#pragma unroll
        for (int j = 0; j < 17; j++) a += s[rr * 170 + j * 10 + c];
        g_cs[(size_t)(r0 + rr) * 12 + c] = a;
    } else if (t < 96) {
        int rr = (t - 80) >> 1;
        // pad: [10] = 1.0 (fsum accumulator), [11] = 0
        g_cs[(size_t)(r0 + rr) * 12 + 10 + ((t - 80) & 1)] =
            ((t - 80) & 1) ? 0.f : 1.f;
    } else if (t < 104) {
        int rr = t - 96;
        const int* rp = rules + (size_t)(r0 + rr) * Dn;
        uint32_t idx[5];
#pragma unroll
        for (int g = 0; g < 4; g++)
            idx[g] = ((uint32_t)rp[3*g] & 3u) | (((uint32_t)rp[3*g+1] & 3u) << 2)
                   | (((uint32_t)rp[3*g+2] & 3u) << 4);
        idx[4] = ((uint32_t)rp[12] & 3u) | (((uint32_t)rp[13] & 3u) << 2)
               | (((uint32_t)rp[14] & 3u) << 4) | (((uint32_t)rp[15] & 3u) << 6);
        uint4 o;
        o.x = ( idx[0]        * 128u) | (((64u  + idx[1]) * 128u) << 16);
        o.y = ((128u + idx[2]) * 128u) | (((192u + idx[3]) * 128u) << 16);
        o.z = (256u + idx[4]) * 128u;
        o.w = 0;
        g_offp[r0 + rr] = o;
    }
}

// ---------------------------------------------------------------------------
// main: 2 CTAs per batch tile (rule-split), 2 CTAs/SM. 512-entry table (64KB).
// ---------------------------------------------------------------------------
// smem floats: tbl 512*32 = 16384 | stage 16*16*34 = 8704 (overlays mf 2048 +
//              pair 1024 during build) | xs 512 | red 12*32 = 384
#define STAGE_FLOATS (WARPS * CHUNK * 34)
#define SMEM_FLOATS  (512 * 32 + STAGE_FLOATS + 512 + 384)
#define SMEM_BYTES   (SMEM_FLOATS * 4)

__global__ void __launch_bounds__(THREADS, 2)
anfis_main(const float* __restrict__ x,
           const float* __restrict__ centers,
           const float* __restrict__ widths,
           float* __restrict__ nf,      // (B, R) raw f written here
           int write_aux) {
    extern __shared__ float sm[];
    float* tbl   = sm;                       // 512*32
    float* stage = tbl + 512 * 32;           // 16*16*34
    float* xs    = stage + STAGE_FLOATS;     // 32*16
    float* red   = xs + 512;                 // 12*32
    float* mf    = stage;                    // overlay (build only)
    float* pair  = stage + 2048;             // overlay (build only), 2*16*32

    const int tid  = threadIdx.x;
    const int w    = tid >> 5;
    const int lane = tid & 31;
    const int tile = blockIdx.x >> 1;
    const int rank = blockIdx.x & 1;
    const int b0   = tile * BT;

    // ---- build phase ----
    for (int i = tid; i < BT * Dn; i += THREADS)
        xs[i] = x[(size_t)b0 * Dn + i];
    if (tid < 384) red[tid] = 0.f;
    __syncthreads();

    for (int e = tid; e < 64 * 32; e += THREADS) {
        int dm = e >> 5, b = e & 31;
        int d = dm >> 2, m = dm & 3;
        float cc = centers[d * Mn + m];
        float ww = widths[d * Mn + m];
        float df = xs[b * Dn + d] - cc;
        mf[dm * 32 + b] = expf(-df * df / (2.f * ww * ww));
    }
    __syncthreads();

    // groups 0-3 (3 dims each, 64 entries each)
    for (int pp = w; pp < 256; pp += WARPS) {
        int g = pp >> 6, idx = pp & 63;
        tbl[pp * 32 + lane] =
            mf[((3*g + 0) * 4 + ( idx       & 3)) * 32 + lane] *
            mf[((3*g + 1) * 4 + ((idx >> 2) & 3)) * 32 + lane] *
            mf[((3*g + 2) * 4 + ( idx >> 4     )) * 32 + lane];
    }
    // pair tables for group 4 (dims 12,13 and 14,15)
    for (int pp = w; pp < 32; pp += WARPS) {
        int grp = pp >> 4, i2 = pp & 15;
        int d0 = 12 + grp * 2;
        pair[pp * 32 + lane] =
            mf[(d0      * 4 + (i2 & 3))  * 32 + lane] *
            mf[((d0+1)  * 4 + (i2 >> 2)) * 32 + lane];
    }
    __syncthreads();
    // group 4 (4 dims, 256 entries)
    for (int pp = w; pp < 256; pp += WARPS) {
        tbl[(256 + pp) * 32 + lane] =
            pair[(pp & 15) * 32 + lane] * pair[(16 + (pp >> 4)) * 32 + lane];
    }
    __syncthreads();   // stage region free from here

    // ---- main loop: 64 rules/warp in chunks of 16 ----
    const char* tb = (const char*)tbl + lane * 4;
    const ulonglong2* cs2 = (const ulonglong2*)g_cs;
    const int rbase = rank * HALF_R + w * RPW;
    float* stg = stage + w * (CHUNK * 34);

    unsigned long long a01 = 0, a23 = 0, a45 = 0, a67 = 0, a89 = 0, aSF = 0;

    for (int ch = 0; ch < RPW / CHUNK; ch++) {
        const int r0 = rbase + ch * CHUNK;
#pragma unroll 4
        for (int rl = 0; rl < CHUNK; rl++) {
            const int r = r0 + rl;
            const uint4 o = g_offp[r];
            float f0 = *(const float*)(tb + (o.x & 0xFFFFu));
            float f1 = *(const float*)(tb + (o.x >> 16));
            float f2 = *(const float*)(tb + (o.y & 0xFFFFu));
            float f3 = *(const float*)(tb + (o.y >> 16));
            float f4 = *(const float*)(tb + o.z);
            float f = ((f0 * f1) * (f2 * f3)) * f4;
            stg[rl * 34 + lane] = f;
            unsigned long long fp = bcast2(f);
            ulonglong2 v0 = cs2[r * 3 + 0];
            ulonglong2 v1 = cs2[r * 3 + 1];
            ulonglong2 v2 = cs2[r * 3 + 2];
            ffma2(a01, fp, v0.x); ffma2(a23, fp, v0.y);
            ffma2(a45, fp, v1.x); ffma2(a67, fp, v1.y);
            ffma2(a89, fp, v2.x); ffma2(aSF, fp, v2.y);  // .lo accumulates fsum
        }
        __syncwarp();
        if (write_aux) {
            // transposed coalesced flush of raw f (conflict-free: stride 34)
#pragma unroll
            for (int t2 = 0; t2 < 16; t2++) {
                int row = 2 * t2 + (lane >> 4);
                int j = lane & 15;
                nf[(size_t)(b0 + row) * Rn + r0 + j] = stg[j * 34 + row];
            }
        }
        __syncwarp();
    }

    // ---- CTA reduction (smem atomics) ----
    {
        union { unsigned long long u; float2 f; } c0, c1, c2, c3, c4, c5;
        c0.u = a01; c1.u = a23; c2.u = a45; c3.u = a67; c4.u = a89; c5.u = aSF;
        atomicAdd(&red[ 0 * 32 + lane], c0.f.x);
        atomicAdd(&red[ 1 * 32 + lane], c0.f.y);
        atomicAdd(&red[ 2 * 32 + lane], c1.f.x);
        atomicAdd(&red[ 3 * 32 + lane], c1.f.y);
        atomicAdd(&red[ 4 * 32 + lane], c2.f.x);
        atomicAdd(&red[ 5 * 32 + lane], c2.f.y);
        atomicAdd(&red[ 6 * 32 + lane], c3.f.x);
        atomicAdd(&red[ 7 * 32 + lane], c3.f.y);
        atomicAdd(&red[ 8 * 32 + lane], c4.f.x);
        atomicAdd(&red[ 9 * 32 + lane], c4.f.y);
        atomicAdd(&red[10 * 32 + lane], c5.f.x);   // fsum
    }
    __syncthreads();

    // deterministic partial writes (no gmem atomics)
    if (tid < 32) {
        g_psum[rank * Bn + b0 + tid] = red[10 * 32 + tid];
        if (rank == 0) {
            float s = 1.f;
#pragma unroll
            for (int d = 0; d < Dn; d++) s += xs[tid * Dn + d];
            g_sx[b0 + tid] = s;
        }
    }
    if (tid < 320) {
        int b = tid & 31, c = tid >> 5;
        g_pacc[(size_t)rank * Bn * Cn + (size_t)(b0 + b) * Cn + c] = red[c * 32 + b];
    }
}

// ---------------------------------------------------------------------------
// normalize: one CTA per batch row. Rescales nf in place, writes out + xext.
// ---------------------------------------------------------------------------
__global__ void __launch_bounds__(256)
anfis_norm(const float* __restrict__ x,
           float* __restrict__ out,
           float* __restrict__ nf,
           float* __restrict__ xext,
           int write_aux) {
    const int b = blockIdx.x;
    const int t = threadIdx.x;
    const float s = g_psum[b] + g_psum[Bn + b];
    const float inv = 1.f / (s + EPSV);

    if (write_aux) {
        float4* row = (float4*)(nf + (size_t)b * Rn);
        float4 v0 = row[t];
        float4 v1 = row[t + 256];
        v0.x *= inv; v0.y *= inv; v0.z *= inv; v0.w *= inv;
        v1.x *= inv; v1.y *= inv; v1.z *= inv; v1.w *= inv;
        row[t] = v0;
        row[t + 256] = v1;
        if (t >= 32 && t < 49) {
            int j = t - 32;
            xext[(size_t)b * (Dn + 1) + j] = (j < Dn) ? x[(size_t)b * Dn + j] : 1.f;
        }
    }
    if (t < Cn) {
        float a = g_pacc[(size_t)b * Cn + t] +
                  g_pacc[(size_t)Bn * Cn + (size_t)b * Cn + t];
        out[(size_t)b * Cn + t] = g_sx[b] * inv * a;
    }
}

// ---------------------------------------------------------------------------
extern "C" void kernel_launch(void* const* d_in, const int* in_sizes, int n_in,
                              void* d_out, int out_size) {
    const float* x       = (const float*)d_in[0];
    const float* centers = (const float*)d_in[1];
    const float* widths  = (const float*)d_in[2];
    const float* cons    = (const float*)d_in[3];
    const int*   rules   = (const int*)d_in[4];

    float* out = (float*)d_out;
    const long total = (long)Bn * Cn + (long)Bn * Rn + (long)Bn * (Dn + 1);
    const int write_aux = (out_size >= total) ? 1 : 0;
    float* nf   = out + (size_t)Bn * Cn;
    float* xext = nf + (size_t)Bn * Rn;

    anfis_prep<<<Rn / 8, 256>>>(cons, rules);

    cudaFuncSetAttribute(anfis_main, cudaFuncAttributeMaxDynamicSharedMemorySize,
                         SMEM_BYTES);
    anfis_main<<<(Bn / BT) * 2, THREADS, SMEM_BYTES>>>(x, centers, widths,
                                                       nf, write_aux);

    anfis_norm<<<Bn, 256>>>(x, out, nf, xext, write_aux);
}